// round 15
// baseline (speedup 1.0000x reference)
#include <cuda_runtime.h>
#include <cuda_bf16.h>
#include <cuda_fp16.h>

// Problem constants (fixed by reference)
#define BB      8
#define NN      2048
#define DD      256
#define KSTEPS  10
#define OUTD    15
#define MAXN    256
#define TOTROWS (BB * NN)   // 16384

// ---- static device scratch (no allocations allowed) ----
// g_AH and g_WlT are stored K-PERMUTED: within each group of 8 consecutive
// k-columns, element k goes to slot (k&3)*2 + ((k>>2)&1)  -> every tf32 mma
// fragment read is a single LDS.64 of the (k, k+4) pair.
// g_AH holds FULL fp32 (no tf32 pre-round): update does a 2xTF32 A-split.
__device__ float          g_H  [TOTROWS * DD];   // 16 MB fp32 master H
__device__ __nv_bfloat16  g_Hbf[TOTROWS * DD];   //  8 MB bf16 mirror (gather source)
__device__ float          g_AH [TOTROWS * DD];   // 16 MB A @ H (fp32, k-permuted)
__device__ float          g_WlT[DD * DD];        // 256 KB Wl^T (tf32-rounded, k-permuted)
__device__ short          g_col[TOTROWS * MAXN]; //  8 MB padded CSR column indices
__device__ int            g_deg[TOTROWS];
__device__ float          g_inv[TOTROWS];        // 1 / max(deg, 1)

// ---- helpers ----
__device__ __forceinline__ float tf32_round(float x) {
    unsigned u;
    asm("cvt.rna.tf32.f32 %0, %1;" : "=r"(u) : "f"(x));
    return __uint_as_float(u);
}

__device__ __forceinline__ void cp_async16(void* dst, const void* src) {
    unsigned d = (unsigned)__cvta_generic_to_shared(dst);
    asm volatile("cp.async.cg.shared.global [%0], [%1], 16;" :: "r"(d), "l"(src));
}

__device__ __forceinline__ void mma_tf32(float c[4], const float a[4],
                                         const unsigned b0, const unsigned b1) {
    asm volatile(
        "mma.sync.aligned.m16n8k8.row.col.f32.tf32.tf32.f32 "
        "{%0,%1,%2,%3}, {%4,%5,%6,%7}, {%8,%9}, {%0,%1,%2,%3};"
        : "+f"(c[0]), "+f"(c[1]), "+f"(c[2]), "+f"(c[3])
        : "r"(__float_as_uint(a[0])), "r"(__float_as_uint(a[1])),
          "r"(__float_as_uint(a[2])), "r"(__float_as_uint(a[3])),
          "r"(b0), "r"(b1));
}

// bf16x2 -> two f32 via byte-permute, accumulate with one packed f32x2 add.
__device__ __forceinline__ void acc_bf16x2(unsigned long long& acc, unsigned u) {
    const unsigned lo = __byte_perm(u, 0, 0x1044);   // {u.b1,u.b0,0,0}
    const unsigned hi = __byte_perm(u, 0, 0x3244);   // {u.b3,u.b2,0,0}
    unsigned long long v;
    asm("mov.b64 %0, {%1, %2};" : "=l"(v) : "r"(lo), "r"(hi));
    asm("add.rn.f32x2 %0, %0, %1;" : "+l"(acc) : "l"(v));
}

__device__ __forceinline__ void unpack2(unsigned long long v, float& lo, float& hi) {
    unsigned a, b;
    asm("mov.b64 {%0, %1}, %2;" : "=r"(a), "=r"(b) : "l"(v));
    lo = __uint_as_float(a);
    hi = __uint_as_float(b);
}

// fast packed tanh: 2 elements per MUFU.TANH
__device__ __forceinline__ float2 tanh2_approx(float x, float y) {
    __half2 hv = __floats2half2_rn(x, y);
    unsigned u = *reinterpret_cast<unsigned*>(&hv);
    asm("tanh.approx.f16x2 %0, %0;" : "+r"(u));
    hv = *reinterpret_cast<__half2*>(&u);
    return __half22float2(hv);
}

// =====================================================================
// Kernel 1: adjacency build. One warp per row: ballot-compact nonzero
// columns of (Yr!=0 || Yi!=0), excluding the diagonal. DRAM-bound.
// =====================================================================
__global__ void __launch_bounds__(256) adj_kernel(const float* __restrict__ Yr,
                                                  const float* __restrict__ Yi) {
    const int warp = (blockIdx.x * blockDim.x + threadIdx.x) >> 5; // global row
    const int lane = threadIdx.x & 31;
    if (warp >= TOTROWS) return;
    const int i = warp & (NN - 1);
    const float* yr = Yr + (size_t)warp * NN;
    const float* yi = Yi + (size_t)warp * NN;
    short* cols = g_col + (size_t)warp * MAXN;

    int count = 0;
    #pragma unroll 4
    for (int j0 = 0; j0 < NN; j0 += 32) {
        const int j = j0 + lane;
        const bool nz = (j != i) && ((yr[j] != 0.0f) || (yi[j] != 0.0f));
        const unsigned m = __ballot_sync(0xffffffffu, nz);
        if (nz) {
            const int pos = count + __popc(m & ((1u << lane) - 1u));
            if (pos < MAXN) cols[pos] = (short)j;
        }
        count += __popc(m);
    }
    if (lane == 0) {
        g_deg[warp] = count < MAXN ? count : MAXN;
        g_inv[warp] = 1.0f / (float)(count > 1 ? count : 1);
    }
}

// =====================================================================
// Kernel 2: role-selected embedding. One block per node, thread = d.
// =====================================================================
__global__ void __launch_bounds__(256) emb_kernel(const int*   __restrict__ bus_type,
                                                  const float* __restrict__ features,
                                                  const float* __restrict__ W_emb,
                                                  const float* __restrict__ b_emb) {
    const int node = blockIdx.x;
    const int d = threadIdx.x;
    const int r = bus_type[node] - 1;          // 0..2
    const float f0 = features[node * 2 + 0];
    const float f1 = features[node * 2 + 1];
    const float w0 = W_emb[(r * 2 + 0) * DD + d];
    const float w1 = W_emb[(r * 2 + 1) * DD + d];
    const float h = tanhf(fmaf(f0, w0, fmaf(f1, w1, b_emb[r * DD + d])));
    g_H  [(size_t)node * DD + d] = h;
    g_Hbf[(size_t)node * DD + d] = __float2bfloat16(h);
}

// =====================================================================
// Kernel 2b: Wl^T, tf32-rounded, k-permuted. WlT[n][perm(k)] = Wl[k][n].
// =====================================================================
__global__ void __launch_bounds__(256) wlt_kernel(const float* __restrict__ Wl) {
    const int n = blockIdx.x;
    const int k = threadIdx.x;
    const int t = k & 7;
    const int kp = (k & ~7) | ((t & 3) * 2 + (t >> 2));
    g_WlT[n * DD + kp] = tf32_round(Wl[k * DD + n]);
}

// =====================================================================
// Kernel 3: SpMM  AH[row,:] = inv * sum_{j} Hbf[j,:]  (fp32, k-permuted).
// One warp per row. Lane owns d = lane*8..+7. bf16 gather; PRMT +
// packed f32x2 adds. Index quads are software-pipelined.
// =====================================================================
__device__ __forceinline__ void accum16(unsigned long long acc[4], const uint4 v) {
    acc_bf16x2(acc[0], v.x);
    acc_bf16x2(acc[1], v.y);
    acc_bf16x2(acc[2], v.z);
    acc_bf16x2(acc[3], v.w);
}

__global__ void __launch_bounds__(256) spmm_kernel() {
    const int lane = threadIdx.x & 31;
    const int row  = blockIdx.x * 8 + (threadIdx.x >> 5);
    const int b = row >> 11;
    const __nv_bfloat16* __restrict__ Hb = g_Hbf + (size_t)b * NN * DD;
    const short* __restrict__ cols = g_col + (size_t)row * MAXN;
    const int deg = g_deg[row];
    const float inv = g_inv[row];

    unsigned long long acc[4];
    #pragma unroll
    for (int q = 0; q < 4; ++q) acc[q] = 0ULL;

    int t = 0;
    if (deg >= 4) {
        ushort4 j4 = *(const ushort4*)(cols);     // prefetched quad
        for (; t + 8 <= deg; t += 4) {
            const ushort4 jn = *(const ushort4*)(cols + t + 4);  // next quad
            const uint4 v0 = *((const uint4*)(Hb + (size_t)j4.x * DD) + lane);
            const uint4 v1 = *((const uint4*)(Hb + (size_t)j4.y * DD) + lane);
            const uint4 v2 = *((const uint4*)(Hb + (size_t)j4.z * DD) + lane);
            const uint4 v3 = *((const uint4*)(Hb + (size_t)j4.w * DD) + lane);
            accum16(acc, v0);
            accum16(acc, v1);
            accum16(acc, v2);
            accum16(acc, v3);
            j4 = jn;
        }
        // last full quad
        const uint4 v0 = *((const uint4*)(Hb + (size_t)j4.x * DD) + lane);
        const uint4 v1 = *((const uint4*)(Hb + (size_t)j4.y * DD) + lane);
        const uint4 v2 = *((const uint4*)(Hb + (size_t)j4.z * DD) + lane);
        const uint4 v3 = *((const uint4*)(Hb + (size_t)j4.w * DD) + lane);
        accum16(acc, v0);
        accum16(acc, v1);
        accum16(acc, v2);
        accum16(acc, v3);
        t += 4;
    }
    for (; t < deg; ++t) {
        const int j0 = cols[t];
        const uint4 v0 = *((const uint4*)(Hb + (size_t)j0 * DD) + lane);
        accum16(acc, v0);
    }

    float a[8];
    unpack2(acc[0], a[0], a[1]);
    unpack2(acc[1], a[2], a[3]);
    unpack2(acc[2], a[4], a[5]);
    unpack2(acc[3], a[6], a[7]);
    #pragma unroll
    for (int q = 0; q < 8; ++q) a[q] *= inv;

    // k-permuted store: slot order within the k8 group = a0,a4,a1,a5,a2,a6,a3,a7
    float4* outp = (float4*)(g_AH + (size_t)row * DD);
    outp[lane * 2 + 0] = make_float4(a[0], a[4], a[1], a[5]);
    outp[lane * 2 + 1] = make_float4(a[2], a[6], a[3], a[7]);
}

// =====================================================================
// Kernel 4: dense update  H += tanh(AH @ Wl + bl).
// 2xTF32 A-split HMMA: hi-term passes raw f32 (HW truncates to tf32),
// lo-term passes the EXACT residual al = a - mask13(a). Removes the
// A-side tf32 rounding error; only Wl's fixed tf32 rounding remains.
// CTA tile 128x128, grid (128,2), 8 warps 4m x 2n, 2-stage cp.async
// pipeline (k-chunk 16), XOR-swizzled SMEM (same as r14, bit-identical
// layout semantics).
// Epilogue: tanh.approx.f16x2 (1 MUFU / 2 elems) — the r14 bottleneck
// was 4.19M libm tanhf calls pinning the MUFU/ALU pipes.
// =====================================================================
__global__ void __launch_bounds__(256, 2) update_kernel(const float* __restrict__ bl) {
    __shared__ float As[2][128 * 16];   // 8 KB per stage
    __shared__ float Bs[2][128 * 16];

    const int tid   = threadIdx.x;
    const int lane  = tid & 31;
    const int wid   = tid >> 5;
    const int mBase = blockIdx.x * 128;
    const int nBase = blockIdx.y * 128;
    const int warpM = (wid & 3) * 32;   // m offset within CTA tile
    const int warpN = (wid >> 2) * 64;  // n offset within CTA tile
    const int gRow  = lane >> 2;        // 0..7
    const int tig   = lane & 3;         // 0..3
    const int swzR  = ((gRow >> 1) & 1) << 2;   // read-side swizzle (64b-word XOR)

    const float* Agbl = g_AH  + (size_t)mBase * DD;
    const float* Bgbl = g_WlT + (size_t)nBase * DD;

    // load mapping: 512 16B-segments per operand per chunk, 2 per thread.
    const int ldRow0 = tid >> 2;
    const int ldSeg0 = tid & 3;
    const int ldRow1 = (tid + 256) >> 2;
    const int ldSeg1 = ldSeg0;
    const int ldOff0 = ldRow0 * 16 + (ldSeg0 ^ (((ldRow0 >> 1) & 1) << 1)) * 4;
    const int ldOff1 = ldRow1 * 16 + (ldSeg1 ^ (((ldRow1 >> 1) & 1) << 1)) * 4;
    const int ldSrc0 = ldRow0 * DD + ldSeg0 * 4;
    const int ldSrc1 = ldRow1 * DD + ldSeg1 * 4;

    float acc[2][8][4];
    #pragma unroll
    for (int i = 0; i < 2; ++i)
        #pragma unroll
        for (int j = 0; j < 8; ++j)
            #pragma unroll
            for (int q = 0; q < 4; ++q) acc[i][j][q] = 0.0f;

    // prologue: issue chunk 0 into stage 0
    cp_async16(&As[0][ldOff0], Agbl + ldSrc0);
    cp_async16(&As[0][ldOff1], Agbl + ldSrc1);
    cp_async16(&Bs[0][ldOff0], Bgbl + ldSrc0);
    cp_async16(&Bs[0][ldOff1], Bgbl + ldSrc1);
    asm volatile("cp.async.commit_group;" ::: "memory");

    #pragma unroll
    for (int c = 0; c < 16; ++c) {
        const int st = c & 1;
        asm volatile("cp.async.wait_group 0;" ::: "memory");
        __syncthreads();

        if (c + 1 < 16) {
            const int kk = (c + 1) * 16;
            const int nx = st ^ 1;
            cp_async16(&As[nx][ldOff0], Agbl + kk + ldSrc0);
            cp_async16(&As[nx][ldOff1], Agbl + kk + ldSrc1);
            cp_async16(&Bs[nx][ldOff0], Bgbl + kk + ldSrc0);
            cp_async16(&Bs[nx][ldOff1], Bgbl + kk + ldSrc1);
            asm volatile("cp.async.commit_group;" ::: "memory");
        }

        #pragma unroll
        for (int ks = 0; ks < 2; ++ks) {
            const int fOff = ((ks * 4 + tig) ^ swzR) * 2;

            float a[2][4], al[2][4];
            #pragma unroll
            for (int i = 0; i < 2; ++i) {
                const float* ap = &As[st][(warpM + i * 16 + gRow) * 16 + fOff];
                const float2 w0 = *(const float2*)ap;            // (k=tig, k=tig+4)
                const float2 w1 = *(const float2*)(ap + 8 * 16); // row+8 (same swizzle)
                a[i][0] = w0.x; a[i][1] = w1.x; a[i][2] = w0.y; a[i][3] = w1.y;
                #pragma unroll
                for (int q = 0; q < 4; ++q) {
                    const float hi = __uint_as_float(__float_as_uint(a[i][q]) & 0xFFFFE000u);
                    al[i][q] = a[i][q] - hi;   // exact residual
                }
            }

            #pragma unroll
            for (int j = 0; j < 8; ++j) {
                const float* bp = &Bs[st][(warpN + j * 8 + gRow) * 16 + fOff];
                const float2 bw = *(const float2*)bp;
                const unsigned b0 = __float_as_uint(bw.x);
                const unsigned b1 = __float_as_uint(bw.y);
                mma_tf32(acc[0][j], a[0],  b0, b1);
                mma_tf32(acc[0][j], al[0], b0, b1);
                mma_tf32(acc[1][j], a[1],  b0, b1);
                mma_tf32(acc[1][j], al[1], b0, b1);
            }
        }
    }

    // fused epilogue: H[m][n] += tanh.approx(acc + bl[n]); bf16 mirror refresh.
    const int cOff = tig * 2;

    float2 bl2[8];
    #pragma unroll
    for (int j = 0; j < 8; ++j)
        bl2[j] = *(const float2*)(bl + nBase + warpN + j * 8 + cOff);

    #pragma unroll
    for (int i = 0; i < 2; ++i) {
        const int r0 = mBase + warpM + i * 16 + gRow;
        const int r1 = r0 + 8;
        #pragma unroll
        for (int j = 0; j < 8; ++j) {
            const int c = nBase + warpN + j * 8 + cOff;
            const float* ac = acc[i][j];

            const float2 t0 = tanh2_approx(ac[0] + bl2[j].x, ac[1] + bl2[j].y);
            float2 h0 = *(float2*)(g_H + (size_t)r0 * DD + c);
            h0.x += t0.x;
            h0.y += t0.y;
            *(float2*)(g_H + (size_t)r0 * DD + c) = h0;
            const __nv_bfloat162 m0 = __floats2bfloat162_rn(h0.x, h0.y);
            *(unsigned*)(g_Hbf + (size_t)r0 * DD + c) = *reinterpret_cast<const unsigned*>(&m0);

            const float2 t1 = tanh2_approx(ac[2] + bl2[j].x, ac[3] + bl2[j].y);
            float2 h1 = *(float2*)(g_H + (size_t)r1 * DD + c);
            h1.x += t1.x;
            h1.y += t1.y;
            *(float2*)(g_H + (size_t)r1 * DD + c) = h1;
            const __nv_bfloat162 m1 = __floats2bfloat162_rn(h1.x, h1.y);
            *(unsigned*)(g_Hbf + (size_t)r1 * DD + c) = *reinterpret_cast<const unsigned*>(&m1);
        }
    }
}

// =====================================================================
// Kernel 5: decoder. Block = batch. Column sums over nodes (coalesced),
// then tiny GEMV. Reads the fp32 master H.
// =====================================================================
__global__ void __launch_bounds__(256) decoder_kernel(const float* __restrict__ Wd,
                                                      const float* __restrict__ bd,
                                                      float* __restrict__ out) {
    const int b = blockIdx.x;
    const int d = threadIdx.x;
    const float* Hb = g_H + (size_t)b * NN * DD;

    float s0 = 0.f, s1 = 0.f, s2 = 0.f, s3 = 0.f;
    #pragma unroll 1
    for (int n = 0; n < NN; n += 4) {
        s0 += Hb[(size_t)(n + 0) * DD + d];
        s1 += Hb[(size_t)(n + 1) * DD + d];
        s2 += Hb[(size_t)(n + 2) * DD + d];
        s3 += Hb[(size_t)(n + 3) * DD + d];
    }
    __shared__ float mean[DD];
    mean[d] = (s0 + s1 + s2 + s3) * (1.0f / (float)NN);
    __syncthreads();

    if (d < OUTD) {
        float o = bd[d];
        #pragma unroll 8
        for (int k = 0; k < DD; ++k)
            o = fmaf(mean[k], Wd[k * OUTD + d], o);
        out[b * OUTD + d] = o;
    }
}

// =====================================================================
// Launch. Inputs (metadata order): 0 bus_type(i32), 1 Yr, 2 Yi,
// 3 features, 4 W_emb, 5 b_emb, 6 Wl, 7 bl, 8 Wd, 9 bd.
// Output: float[8*15].
// =====================================================================
extern "C" void kernel_launch(void* const* d_in, const int* in_sizes, int n_in,
                              void* d_out, int out_size) {
    const int*   bus_type = (const int*)  d_in[0];
    const float* Yr       = (const float*)d_in[1];
    const float* Yi       = (const float*)d_in[2];
    const float* features = (const float*)d_in[3];
    const float* W_emb    = (const float*)d_in[4];
    const float* b_emb    = (const float*)d_in[5];
    const float* Wl       = (const float*)d_in[6];
    const float* bl       = (const float*)d_in[7];
    const float* Wd       = (const float*)d_in[8];
    const float* bd       = (const float*)d_in[9];
    float* out = (float*)d_out;

    adj_kernel<<<TOTROWS / 8, 256>>>(Yr, Yi);
    emb_kernel<<<TOTROWS, 256>>>(bus_type, features, W_emb, b_emb);
    wlt_kernel<<<DD, DD>>>(Wl);

    for (int k = 0; k < KSTEPS; ++k) {
        spmm_kernel<<<TOTROWS / 8, 256>>>();
        update_kernel<<<dim3(TOTROWS / 128, 2), 256>>>(bl);
    }

    decoder_kernel<<<BB, 256>>>(Wd, bd, out);
}

// round 16
// speedup vs baseline: 1.0476x; 1.0476x over previous
#include <cuda_runtime.h>
#include <cuda_bf16.h>

// Problem constants (fixed by reference)
#define BB      8
#define NN      2048
#define DD      256
#define KSTEPS  10
#define OUTD    15
#define MAXN    256
#define TOTROWS (BB * NN)   // 16384

// ---- static device scratch (no allocations allowed) ----
// g_AH and g_WlT are stored K-PERMUTED: within each group of 8 consecutive
// k-columns, element k goes to slot (k&3)*2 + ((k>>2)&1)  -> every tf32 mma
// fragment read is a single LDS.64 of the (k, k+4) pair.
__device__ float          g_H  [TOTROWS * DD];   // 16 MB fp32 master H
__device__ __nv_bfloat16  g_Hbf[TOTROWS * DD];   //  8 MB bf16 mirror (gather source)
__device__ float          g_AH [TOTROWS * DD];   // 16 MB A @ H (tf32-rounded, k-permuted)
__device__ float          g_WlT[DD * DD];        // 256 KB Wl^T (tf32-rounded, k-permuted)
__device__ short          g_col[TOTROWS * MAXN]; //  8 MB padded CSR column indices
__device__ int            g_deg[TOTROWS];
__device__ float          g_inv[TOTROWS];        // 1 / max(deg, 1)

// ---- helpers ----
__device__ __forceinline__ float tf32_round(float x) {
    unsigned u;
    asm("cvt.rna.tf32.f32 %0, %1;" : "=r"(u) : "f"(x));
    return __uint_as_float(u);
}

__device__ __forceinline__ void cp_async16(void* dst, const void* src) {
    unsigned d = (unsigned)__cvta_generic_to_shared(dst);
    asm volatile("cp.async.cg.shared.global [%0], [%1], 16;" :: "r"(d), "l"(src));
}

__device__ __forceinline__ void mma_tf32(float c[4], const unsigned a[4],
                                         const unsigned b0, const unsigned b1) {
    asm volatile(
        "mma.sync.aligned.m16n8k8.row.col.f32.tf32.tf32.f32 "
        "{%0,%1,%2,%3}, {%4,%5,%6,%7}, {%8,%9}, {%0,%1,%2,%3};"
        : "+f"(c[0]), "+f"(c[1]), "+f"(c[2]), "+f"(c[3])
        : "r"(a[0]), "r"(a[1]), "r"(a[2]), "r"(a[3]), "r"(b0), "r"(b1));
}

// bf16x2 -> two f32 via byte-permute, accumulate with one packed f32x2 add.
__device__ __forceinline__ void acc_bf16x2(unsigned long long& acc, unsigned u) {
    const unsigned lo = __byte_perm(u, 0, 0x1044);   // {u.b1,u.b0,0,0}
    const unsigned hi = __byte_perm(u, 0, 0x3244);   // {u.b3,u.b2,0,0}
    unsigned long long v;
    asm("mov.b64 %0, {%1, %2};" : "=l"(v) : "r"(lo), "r"(hi));
    asm("add.rn.f32x2 %0, %0, %1;" : "+l"(acc) : "l"(v));
}

__device__ __forceinline__ void unpack2(unsigned long long v, float& lo, float& hi) {
    unsigned a, b;
    asm("mov.b64 {%0, %1}, %2;" : "=r"(a), "=r"(b) : "l"(v));
    lo = __uint_as_float(a);
    hi = __uint_as_float(b);
}

// hardware tanh: 1 MUFU op, fp32 in/out (no f16 quantization)
__device__ __forceinline__ float tanhf_fast(float x) {
    float y;
    asm("tanh.approx.f32 %0, %1;" : "=f"(y) : "f"(x));
    return y;
}

// =====================================================================
// Kernel 1: adjacency build. One warp per row: ballot-compact nonzero
// columns of (Yr!=0 || Yi!=0), excluding the diagonal. DRAM-bound.
// =====================================================================
__global__ void __launch_bounds__(256) adj_kernel(const float* __restrict__ Yr,
                                                  const float* __restrict__ Yi) {
    const int warp = (blockIdx.x * blockDim.x + threadIdx.x) >> 5; // global row
    const int lane = threadIdx.x & 31;
    if (warp >= TOTROWS) return;
    const int i = warp & (NN - 1);
    const float* yr = Yr + (size_t)warp * NN;
    const float* yi = Yi + (size_t)warp * NN;
    short* cols = g_col + (size_t)warp * MAXN;

    int count = 0;
    #pragma unroll 4
    for (int j0 = 0; j0 < NN; j0 += 32) {
        const int j = j0 + lane;
        const bool nz = (j != i) && ((yr[j] != 0.0f) || (yi[j] != 0.0f));
        const unsigned m = __ballot_sync(0xffffffffu, nz);
        if (nz) {
            const int pos = count + __popc(m & ((1u << lane) - 1u));
            if (pos < MAXN) cols[pos] = (short)j;
        }
        count += __popc(m);
    }
    if (lane == 0) {
        g_deg[warp] = count < MAXN ? count : MAXN;
        g_inv[warp] = 1.0f / (float)(count > 1 ? count : 1);
    }
}

// =====================================================================
// Kernel 2: role-selected embedding. One block per node, thread = d.
// (keeps libm tanhf: runs once, negligible, protects base accuracy)
// =====================================================================
__global__ void __launch_bounds__(256) emb_kernel(const int*   __restrict__ bus_type,
                                                  const float* __restrict__ features,
                                                  const float* __restrict__ W_emb,
                                                  const float* __restrict__ b_emb) {
    const int node = blockIdx.x;
    const int d = threadIdx.x;
    const int r = bus_type[node] - 1;          // 0..2
    const float f0 = features[node * 2 + 0];
    const float f1 = features[node * 2 + 1];
    const float w0 = W_emb[(r * 2 + 0) * DD + d];
    const float w1 = W_emb[(r * 2 + 1) * DD + d];
    const float h = tanhf(fmaf(f0, w0, fmaf(f1, w1, b_emb[r * DD + d])));
    g_H  [(size_t)node * DD + d] = h;
    g_Hbf[(size_t)node * DD + d] = __float2bfloat16(h);
}

// =====================================================================
// Kernel 2b: Wl^T, tf32-rounded, k-permuted. WlT[n][perm(k)] = Wl[k][n].
// =====================================================================
__global__ void __launch_bounds__(256) wlt_kernel(const float* __restrict__ Wl) {
    const int n = blockIdx.x;
    const int k = threadIdx.x;
    const int t = k & 7;
    const int kp = (k & ~7) | ((t & 3) * 2 + (t >> 2));
    g_WlT[n * DD + kp] = tf32_round(Wl[k * DD + n]);
}

// =====================================================================
// Kernel 3: SpMM  AH[row,:] = tf32( inv * sum_{j} Hbf[j,:] ), k-permuted.
// One warp per row. Lane owns d = lane*8..+7. bf16 gather; PRMT +
// packed f32x2 adds. Index quads are software-pipelined.
// =====================================================================
__device__ __forceinline__ void accum16(unsigned long long acc[4], const uint4 v) {
    acc_bf16x2(acc[0], v.x);
    acc_bf16x2(acc[1], v.y);
    acc_bf16x2(acc[2], v.z);
    acc_bf16x2(acc[3], v.w);
}

__global__ void __launch_bounds__(256) spmm_kernel() {
    const int lane = threadIdx.x & 31;
    const int row  = blockIdx.x * 8 + (threadIdx.x >> 5);
    const int b = row >> 11;
    const __nv_bfloat16* __restrict__ Hb = g_Hbf + (size_t)b * NN * DD;
    const short* __restrict__ cols = g_col + (size_t)row * MAXN;
    const int deg = g_deg[row];
    const float inv = g_inv[row];

    unsigned long long acc[4];
    #pragma unroll
    for (int q = 0; q < 4; ++q) acc[q] = 0ULL;

    int t = 0;
    if (deg >= 4) {
        ushort4 j4 = *(const ushort4*)(cols);     // prefetched quad
        for (; t + 8 <= deg; t += 4) {
            const ushort4 jn = *(const ushort4*)(cols + t + 4);  // next quad
            const uint4 v0 = *((const uint4*)(Hb + (size_t)j4.x * DD) + lane);
            const uint4 v1 = *((const uint4*)(Hb + (size_t)j4.y * DD) + lane);
            const uint4 v2 = *((const uint4*)(Hb + (size_t)j4.z * DD) + lane);
            const uint4 v3 = *((const uint4*)(Hb + (size_t)j4.w * DD) + lane);
            accum16(acc, v0);
            accum16(acc, v1);
            accum16(acc, v2);
            accum16(acc, v3);
            j4 = jn;
        }
        // last full quad
        const uint4 v0 = *((const uint4*)(Hb + (size_t)j4.x * DD) + lane);
        const uint4 v1 = *((const uint4*)(Hb + (size_t)j4.y * DD) + lane);
        const uint4 v2 = *((const uint4*)(Hb + (size_t)j4.z * DD) + lane);
        const uint4 v3 = *((const uint4*)(Hb + (size_t)j4.w * DD) + lane);
        accum16(acc, v0);
        accum16(acc, v1);
        accum16(acc, v2);
        accum16(acc, v3);
        t += 4;
    }
    for (; t < deg; ++t) {
        const int j0 = cols[t];
        const uint4 v0 = *((const uint4*)(Hb + (size_t)j0 * DD) + lane);
        accum16(acc, v0);
    }

    float a[8];
    unpack2(acc[0], a[0], a[1]);
    unpack2(acc[1], a[2], a[3]);
    unpack2(acc[2], a[4], a[5]);
    unpack2(acc[3], a[6], a[7]);
    #pragma unroll
    for (int q = 0; q < 8; ++q) a[q] = tf32_round(a[q] * inv);

    // k-permuted store: slot order within the k8 group = a0,a4,a1,a5,a2,a6,a3,a7
    float4* outp = (float4*)(g_AH + (size_t)row * DD);
    outp[lane * 2 + 0] = make_float4(a[0], a[4], a[1], a[5]);
    outp[lane * 2 + 1] = make_float4(a[2], a[6], a[3], a[7]);
}

// =====================================================================
// Kernel 4: dense update  H += tanh(AH @ Wl + bl)  via tf32 HMMA
// (mma.sync.m16n8k8, fp32 accum). CTA tile 128m x 128n, grid (128,2),
// 8 warps as 4m x 2n -> warp tile 32m x 64n.
// 2-stage double-buffered cp.async pipeline, k-chunk 16 (16 chunks),
// one __syncthreads per chunk; chunk c+1 loads fly during compute of c.
// SMEM: PITCH 16, XOR-4 swizzle on 64-bit words (write side = 16B-seg
// swizzle physSeg = seg ^ (((row>>1)&1)<<1)). Bit-identical layout
// semantics to R14 (the 999.3us best).
// ONLY change vs R14: epilogue tanhf -> tanh.approx.f32 (1 MUFU op,
// fp32 I/O). R15 showed the f16x2 variant + A-split regressed; this
// isolates the tanh variable.
// =====================================================================
__global__ void __launch_bounds__(256, 2) update_kernel(const float* __restrict__ bl) {
    __shared__ float As[2][128 * 16];   // 8 KB per stage
    __shared__ float Bs[2][128 * 16];

    const int tid   = threadIdx.x;
    const int lane  = tid & 31;
    const int wid   = tid >> 5;
    const int mBase = blockIdx.x * 128;
    const int nBase = blockIdx.y * 128;
    const int warpM = (wid & 3) * 32;   // m offset within CTA tile
    const int warpN = (wid >> 2) * 64;  // n offset within CTA tile
    const int gRow  = lane >> 2;        // 0..7
    const int tig   = lane & 3;         // 0..3
    const int swzR  = ((gRow >> 1) & 1) << 2;   // read-side swizzle (64b-word XOR)

    const float* Agbl = g_AH  + (size_t)mBase * DD;
    const float* Bgbl = g_WlT + (size_t)nBase * DD;

    // load mapping: 512 16B-segments per operand per chunk, 2 per thread.
    // s in {tid, tid+256}; row = s>>2 (0..127), seg = s&3 (0..3).
    const int ldRow0 = tid >> 2;
    const int ldSeg0 = tid & 3;
    const int ldRow1 = (tid + 256) >> 2;
    const int ldSeg1 = ldSeg0;   // (tid+256)&3 == tid&3
    const int ldOff0 = ldRow0 * 16 + (ldSeg0 ^ (((ldRow0 >> 1) & 1) << 1)) * 4;
    const int ldOff1 = ldRow1 * 16 + (ldSeg1 ^ (((ldRow1 >> 1) & 1) << 1)) * 4;
    const int ldSrc0 = ldRow0 * DD + ldSeg0 * 4;
    const int ldSrc1 = ldRow1 * DD + ldSeg1 * 4;

    float acc[2][8][4];
    #pragma unroll
    for (int i = 0; i < 2; ++i)
        #pragma unroll
        for (int j = 0; j < 8; ++j)
            #pragma unroll
            for (int q = 0; q < 4; ++q) acc[i][j][q] = 0.0f;

    // prologue: issue chunk 0 into stage 0
    cp_async16(&As[0][ldOff0], Agbl + ldSrc0);
    cp_async16(&As[0][ldOff1], Agbl + ldSrc1);
    cp_async16(&Bs[0][ldOff0], Bgbl + ldSrc0);
    cp_async16(&Bs[0][ldOff1], Bgbl + ldSrc1);
    asm volatile("cp.async.commit_group;" ::: "memory");

    #pragma unroll
    for (int c = 0; c < 16; ++c) {
        const int st = c & 1;
        asm volatile("cp.async.wait_group 0;" ::: "memory");
        __syncthreads();

        if (c + 1 < 16) {
            const int kk = (c + 1) * 16;
            const int nx = st ^ 1;
            cp_async16(&As[nx][ldOff0], Agbl + kk + ldSrc0);
            cp_async16(&As[nx][ldOff1], Agbl + kk + ldSrc1);
            cp_async16(&Bs[nx][ldOff0], Bgbl + kk + ldSrc0);
            cp_async16(&Bs[nx][ldOff1], Bgbl + kk + ldSrc1);
            asm volatile("cp.async.commit_group;" ::: "memory");
        }

        #pragma unroll
        for (int ks = 0; ks < 2; ++ks) {
            // 64-bit word w = ks*4 + tig, swizzled; float offset = phys*2
            const int fOff = ((ks * 4 + tig) ^ swzR) * 2;

            unsigned a[2][4];
            #pragma unroll
            for (int i = 0; i < 2; ++i) {
                const float* ap = &As[st][(warpM + i * 16 + gRow) * 16 + fOff];
                const float2 w0 = *(const float2*)ap;            // (k=tig, k=tig+4)
                const float2 w1 = *(const float2*)(ap + 8 * 16); // row+8 (same swizzle)
                a[i][0] = __float_as_uint(w0.x);
                a[i][1] = __float_as_uint(w1.x);
                a[i][2] = __float_as_uint(w0.y);
                a[i][3] = __float_as_uint(w1.y);
            }

            #pragma unroll
            for (int j = 0; j < 8; ++j) {
                const float* bp = &Bs[st][(warpN + j * 8 + gRow) * 16 + fOff];
                const float2 bw = *(const float2*)bp;
                const unsigned b0 = __float_as_uint(bw.x);
                const unsigned b1 = __float_as_uint(bw.y);
                mma_tf32(acc[0][j], a[0], b0, b1);
                mma_tf32(acc[1][j], a[1], b0, b1);
            }
        }
    }

    // fused epilogue: H[m][n] += tanh.approx.f32(acc + bl[n]); bf16 mirror.
    const int cOff = tig * 2;

    float2 bl2[8];
    #pragma unroll
    for (int j = 0; j < 8; ++j)
        bl2[j] = *(const float2*)(bl + nBase + warpN + j * 8 + cOff);

    #pragma unroll
    for (int i = 0; i < 2; ++i) {
        const int r0 = mBase + warpM + i * 16 + gRow;
        const int r1 = r0 + 8;
        #pragma unroll
        for (int j = 0; j < 8; ++j) {
            const int c = nBase + warpN + j * 8 + cOff;
            const float* ac = acc[i][j];

            float2 h0 = *(float2*)(g_H + (size_t)r0 * DD + c);
            h0.x += tanhf_fast(ac[0] + bl2[j].x);
            h0.y += tanhf_fast(ac[1] + bl2[j].y);
            *(float2*)(g_H + (size_t)r0 * DD + c) = h0;
            const __nv_bfloat162 m0 = __floats2bfloat162_rn(h0.x, h0.y);
            *(unsigned*)(g_Hbf + (size_t)r0 * DD + c) = *reinterpret_cast<const unsigned*>(&m0);

            float2 h1 = *(float2*)(g_H + (size_t)r1 * DD + c);
            h1.x += tanhf_fast(ac[2] + bl2[j].x);
            h1.y += tanhf_fast(ac[3] + bl2[j].y);
            *(float2*)(g_H + (size_t)r1 * DD + c) = h1;
            const __nv_bfloat162 m1 = __floats2bfloat162_rn(h1.x, h1.y);
            *(unsigned*)(g_Hbf + (size_t)r1 * DD + c) = *reinterpret_cast<const unsigned*>(&m1);
        }
    }
}

// =====================================================================
// Kernel 5: decoder. Block = batch. Column sums over nodes (coalesced),
// then tiny GEMV. Reads the fp32 master H.
// =====================================================================
__global__ void __launch_bounds__(256) decoder_kernel(const float* __restrict__ Wd,
                                                      const float* __restrict__ bd,
                                                      float* __restrict__ out) {
    const int b = blockIdx.x;
    const int d = threadIdx.x;
    const float* Hb = g_H + (size_t)b * NN * DD;

    float s0 = 0.f, s1 = 0.f, s2 = 0.f, s3 = 0.f;
    #pragma unroll 1
    for (int n = 0; n < NN; n += 4) {
        s0 += Hb[(size_t)(n + 0) * DD + d];
        s1 += Hb[(size_t)(n + 1) * DD + d];
        s2 += Hb[(size_t)(n + 2) * DD + d];
        s3 += Hb[(size_t)(n + 3) * DD + d];
    }
    __shared__ float mean[DD];
    mean[d] = (s0 + s1 + s2 + s3) * (1.0f / (float)NN);
    __syncthreads();

    if (d < OUTD) {
        float o = bd[d];
        #pragma unroll 8
        for (int k = 0; k < DD; ++k)
            o = fmaf(mean[k], Wd[k * OUTD + d], o);
        out[b * OUTD + d] = o;
    }
}

// =====================================================================
// Launch. Inputs (metadata order): 0 bus_type(i32), 1 Yr, 2 Yi,
// 3 features, 4 W_emb, 5 b_emb, 6 Wl, 7 bl, 8 Wd, 9 bd.
// Output: float[8*15].
// =====================================================================
extern "C" void kernel_launch(void* const* d_in, const int* in_sizes, int n_in,
                              void* d_out, int out_size) {
    const int*   bus_type = (const int*)  d_in[0];
    const float* Yr       = (const float*)d_in[1];
    const float* Yi       = (const float*)d_in[2];
    const float* features = (const float*)d_in[3];
    const float* W_emb    = (const float*)d_in[4];
    const float* b_emb    = (const float*)d_in[5];
    const float* Wl       = (const float*)d_in[6];
    const float* bl       = (const float*)d_in[7];
    const float* Wd       = (const float*)d_in[8];
    const float* bd       = (const float*)d_in[9];
    float* out = (float*)d_out;

    adj_kernel<<<TOTROWS / 8, 256>>>(Yr, Yi);
    emb_kernel<<<TOTROWS, 256>>>(bus_type, features, W_emb, b_emb);
    wlt_kernel<<<DD, DD>>>(Wl);

    for (int k = 0; k < KSTEPS; ++k) {
        spmm_kernel<<<TOTROWS / 8, 256>>>();
        update_kernel<<<dim3(TOTROWS / 128, 2), 256>>>(bl);
    }

    decoder_kernel<<<BB, 256>>>(Wd, bd, out);
}